// round 8
// baseline (speedup 1.0000x reference)
#include <cuda_runtime.h>
#include <cuda_bf16.h>
#include <cstdint>

#define B_ 2
#define T_ 2048
#define HID_ 2048
#define NH_ 16
#define KVH_ 4
#define HD_ 128
#define NQKV 3072
#define KDIM 2048          // real GEMM K
#define QMAX 32512.0f      // 127*255 + 127

typedef __nv_bfloat16 bf16;

// fp32 intermediates
__device__ float g_qkv[(size_t)B_ * T_ * NQKV];     // [4096][3072]
__device__ float g_ctx[(size_t)B_ * T_ * HID_];     // [4096][2048]
// int8 2-limb operands. A-side: [m][2K] bytes; per 64-k chunk: [a1 x64 | a2 x64]
__device__ signed char g_a_hid[(size_t)4096 * 2 * KDIM];
__device__ signed char g_a_ctx[(size_t)4096 * 2 * KDIM];
// B-side transposed: [n][2K] bytes, same chunk layout
__device__ signed char g_bt_qkv[(size_t)NQKV * 2 * KDIM];
__device__ signed char g_bt_wo[(size_t)2048 * 2 * KDIM];
// scales
__device__ float g_rm_hid[4096];
__device__ float g_rm_ctx[4096];
__device__ float g_cm_qkv[NQKV];
__device__ float g_cm_wo[2048];
// flash hi/lo inputs
__device__ bf16 g_qh[(size_t)B_ * T_ * NH_ * HD_];
__device__ bf16 g_ql[(size_t)B_ * T_ * NH_ * HD_];
__device__ bf16 g_kh[(size_t)B_ * T_ * KVH_ * HD_];
__device__ bf16 g_kl[(size_t)B_ * T_ * KVH_ * HD_];
__device__ bf16 g_vh[(size_t)B_ * T_ * KVH_ * HD_];
__device__ bf16 g_vl[(size_t)B_ * T_ * KVH_ * HD_];

// ---------------------------------------------------------------------------
// helpers
// ---------------------------------------------------------------------------
__device__ __forceinline__ void cp16(uint32_t s, const void* g) {
    asm volatile("cp.async.cg.shared.global [%0], [%1], 16;\n" :: "r"(s), "l"(g));
}
__device__ __forceinline__ void cp_commit() {
    asm volatile("cp.async.commit_group;\n" ::);
}
__device__ __forceinline__ void mma16816(float* c, const uint32_t* a, const uint32_t* b) {
    asm volatile(
        "mma.sync.aligned.m16n8k16.row.col.f32.bf16.bf16.f32 "
        "{%0,%1,%2,%3}, {%4,%5,%6,%7}, {%8,%9}, {%0,%1,%2,%3};\n"
        : "+f"(c[0]), "+f"(c[1]), "+f"(c[2]), "+f"(c[3])
        : "r"(a[0]), "r"(a[1]), "r"(a[2]), "r"(a[3]), "r"(b[0]), "r"(b[1]));
}
__device__ __forceinline__ void mma_s8(int* c, const uint32_t* a, const uint32_t* b) {
    asm volatile(
        "mma.sync.aligned.m16n8k32.row.col.s32.s8.s8.s32 "
        "{%0,%1,%2,%3}, {%4,%5,%6,%7}, {%8,%9}, {%0,%1,%2,%3};\n"
        : "+r"(c[0]), "+r"(c[1]), "+r"(c[2]), "+r"(c[3])
        : "r"(a[0]), "r"(a[1]), "r"(a[2]), "r"(a[3]), "r"(b[0]), "r"(b[1]));
}
__device__ __forceinline__ void ldsm4(uint32_t* d, uint32_t addr) {
    asm volatile("ldmatrix.sync.aligned.m8n8.x4.shared.b16 {%0,%1,%2,%3}, [%4];\n"
                 : "=r"(d[0]), "=r"(d[1]), "=r"(d[2]), "=r"(d[3]) : "r"(addr));
}
__device__ __forceinline__ void ldsm4t(uint32_t* d, uint32_t addr) {
    asm volatile("ldmatrix.sync.aligned.m8n8.x4.trans.shared.b16 {%0,%1,%2,%3}, [%4];\n"
                 : "=r"(d[0]), "=r"(d[1]), "=r"(d[2]), "=r"(d[3]) : "r"(addr));
}
__device__ __forceinline__ float ex2(float x) {
    float r;
    asm("ex2.approx.f32 %0, %1;" : "=f"(r) : "f"(x));
    return r;
}
__device__ __forceinline__ uint32_t packbf2(float a, float b) {
    __nv_bfloat162 t = __floats2bfloat162_rn(a, b);
    return *(uint32_t*)&t;
}
__device__ __forceinline__ void quant2(float x, float s, signed char& q1, signed char& q2) {
    float q = rintf(x * s);
    int a1 = (int)rintf(q * (1.0f / 255.0f));
    int a2 = (int)q - 255 * a1;
    q1 = (signed char)a1;
    q2 = (signed char)a2;
}

// ---------------------------------------------------------------------------
// scale reductions
// ---------------------------------------------------------------------------
// one block per row of A[rows][K]
__global__ void rowmax_kernel(const float* __restrict__ A, float* __restrict__ out, int K) {
    __shared__ float red[8];
    int row = blockIdx.x;
    const float* p = A + (size_t)row * K;
    float m = 1e-30f;
    for (int k = threadIdx.x; k < K; k += 256) m = fmaxf(m, fabsf(p[k]));
#pragma unroll
    for (int off = 16; off; off >>= 1) m = fmaxf(m, __shfl_xor_sync(0xffffffffu, m, off));
    if ((threadIdx.x & 31) == 0) red[threadIdx.x >> 5] = m;
    __syncthreads();
    if (threadIdx.x == 0) {
        float r = red[0];
#pragma unroll
        for (int i = 1; i < 8; i++) r = fmaxf(r, red[i]);
        out[row] = r;
    }
}

// column absmax of W[K][N] (coalesced row sweeps); one thread per column
__global__ void colmax_kernel(const float* __restrict__ W, float* __restrict__ out,
                              int K, int N) {
    int n = blockIdx.x * blockDim.x + threadIdx.x;
    if (n >= N) return;
    float m = 1e-30f;
    for (int k = 0; k < K; k += 4) {
        m = fmaxf(m, fabsf(W[(size_t)k * N + n]));
        m = fmaxf(m, fabsf(W[(size_t)(k + 1) * N + n]));
        m = fmaxf(m, fabsf(W[(size_t)(k + 2) * N + n]));
        m = fmaxf(m, fabsf(W[(size_t)(k + 3) * N + n]));
    }
    out[n] = m;
}

// ---------------------------------------------------------------------------
// quantization
// ---------------------------------------------------------------------------
// A [M][K] fp32 -> [M][2K] int8 (per 64-chunk: a1[64] | a2[64]); 4 elems/thread
__global__ void quantA_kernel(const float* __restrict__ X, const float* __restrict__ rmax,
                              signed char* __restrict__ out, int M, int K) {
    int idx = blockIdx.x * blockDim.x + threadIdx.x;
    int K4 = K >> 2;
    if (idx >= M * K4) return;
    int m = idx / K4;
    int k = (idx - m * K4) << 2;
    float s = QMAX / rmax[m];
    float4 x = *(const float4*)(X + (size_t)m * K + k);
    signed char h[4], l[4];
    quant2(x.x, s, h[0], l[0]);
    quant2(x.y, s, h[1], l[1]);
    quant2(x.z, s, h[2], l[2]);
    quant2(x.w, s, h[3], l[3]);
    size_t base = (size_t)m * (2 * K) + ((k >> 6) << 7) + (k & 63);
    *(char4*)&out[base] = make_char4(h[0], h[1], h[2], h[3]);
    *(char4*)&out[base + 64] = make_char4(l[0], l[1], l[2], l[3]);
}

// W [K][N] fp32 -> out rows [n][2K] int8 via smem transpose. Block (32,8),
// tile 32k x 32n. noff: column offset into out/cmax arrays.
__global__ void quantBt_kernel(const float* __restrict__ W, const float* __restrict__ cmax,
                               signed char* __restrict__ out, int K, int N, int noff) {
    __shared__ float tile[32][33];
    int k0 = blockIdx.y * 32, n0 = blockIdx.x * 32;
    int tx = threadIdx.x, ty = threadIdx.y;
#pragma unroll
    for (int j = 0; j < 4; j++) {
        int r = ty + j * 8;
        tile[r][tx] = W[(size_t)(k0 + r) * N + n0 + tx];
    }
    __syncthreads();
#pragma unroll
    for (int j = 0; j < 4; j++) {
        int nl = ty + j * 8;
        int n = n0 + nl;
        int k = k0 + tx;
        float s = QMAX / cmax[noff + n];
        signed char h, l;
        quant2(tile[tx][nl], s, h, l);
        size_t base = (size_t)(noff + n) * (2 * K) + ((k >> 6) << 7) + (k & 63);
        out[base] = h;
        out[base + 64] = l;
    }
}

// ---------------------------------------------------------------------------
// int8 2-limb GEMM: C(M,N) fp32 = dequant(A) @ dequant(B)^T.
// CTA 128x128, k-chunk 64 (2 x k32 MMA steps), 3-stage cp.async, 256 thr,
// warp tile 64x32. Classes: X=a1b1 (w=255^2), Y=a1b2+a2b1 (w=255).
// ---------------------------------------------------------------------------
#define IST (128 * 128 * 2)   // 32 KB per stage (A 16K + B 16K)

__global__ __launch_bounds__(256, 1) void i8gemm(const signed char* __restrict__ A12,
                                                 const signed char* __restrict__ B12t,
                                                 float* __restrict__ C,
                                                 const float* __restrict__ rmA,
                                                 const float* __restrict__ cmB,
                                                 int M, int N, int K) {
    extern __shared__ char sm[];
    const uint32_t smBase = (uint32_t)__cvta_generic_to_shared(sm);
    const uint32_t bOff = 128 * 128;

    const int tid = threadIdx.x;
    const int warp = tid >> 5, lane = tid & 31;
    const int bm = blockIdx.y, bn = blockIdx.x;
    const int wm = warp >> 2;
    const int wn = warp & 3;
    const int K2 = 2 * K;
    const int KT = K / 64;

    int accX[4][4][4], accY[4][4][4];
#pragma unroll
    for (int mi = 0; mi < 4; mi++)
#pragma unroll
        for (int ni = 0; ni < 4; ni++)
#pragma unroll
            for (int e = 0; e < 4; e++) { accX[mi][ni][e] = 0; accY[mi][ni][e] = 0; }

    auto load_stage = [&](int sidx, int kt) {
        const uint32_t sb = smBase + sidx * IST;
#pragma unroll
        for (int i = 0; i < 8; i++) {
            int q = tid + i * 256;
            int r = q >> 3, c = q & 7;
            if (r < 128) {
                cp16(sb + r * 128 + (((c ^ (r & 7)) & 7) << 4),
                     A12 + (size_t)(bm * 128 + r) * K2 + kt * 128 + c * 16);
            } else {
                int rb = r - 128;
                cp16(sb + bOff + rb * 128 + (((c ^ (rb & 7)) & 7) << 4),
                     B12t + (size_t)(bn * 128 + rb) * K2 + kt * 128 + c * 16);
            }
        }
    };

    load_stage(0, 0);
    cp_commit();
    load_stage(1, 1);
    cp_commit();
    asm volatile("cp.async.wait_group 1;\n" ::);
    __syncthreads();

    const int a_row = wm * 64 + (lane & 15);
    const int a_ch = (lane >> 4);                                   // 0/1
    const int b_row0 = wn * 32 + (lane & 7) + ((lane >> 4) & 1) * 8;
    const int b_ch = (lane >> 3) & 1;

    for (int kt = 0; kt < KT; kt++) {
        const int cur = kt % 3;
        if (kt + 2 < KT) load_stage((kt + 2) % 3, kt + 2);
        cp_commit();

        const uint32_t aS = smBase + cur * IST;
        const uint32_t bS = aS + bOff;

#pragma unroll
        for (int ks = 0; ks < 2; ks++) {
            uint32_t a1f[4][4], a2f[4][4];
#pragma unroll
            for (int mi = 0; mi < 4; mi++) {
                int row = a_row + mi * 16;
                int c1 = ks * 2 + a_ch;
                ldsm4(a1f[mi], aS + row * 128 + (((c1 ^ (row & 7)) & 7) << 4));
                int c2 = c1 + 4;
                ldsm4(a2f[mi], aS + row * 128 + (((c2 ^ (row & 7)) & 7) << 4));
            }
            uint32_t b1f[4][2], b2f[4][2];
#pragma unroll
            for (int np = 0; np < 2; np++) {
                int row = b_row0 + np * 16;
                int c1 = ks * 2 + b_ch;
                uint32_t t4[4];
                ldsm4(t4, bS + row * 128 + (((c1 ^ (row & 7)) & 7) << 4));
                b1f[np * 2][0] = t4[0]; b1f[np * 2][1] = t4[1];
                b1f[np * 2 + 1][0] = t4[2]; b1f[np * 2 + 1][1] = t4[3];
                int c2 = c1 + 4;
                ldsm4(t4, bS + row * 128 + (((c2 ^ (row & 7)) & 7) << 4));
                b2f[np * 2][0] = t4[0]; b2f[np * 2][1] = t4[1];
                b2f[np * 2 + 1][0] = t4[2]; b2f[np * 2 + 1][1] = t4[3];
            }
#pragma unroll
            for (int mi = 0; mi < 4; mi++)
#pragma unroll
                for (int ni = 0; ni < 4; ni++) {
                    mma_s8(accX[mi][ni], a1f[mi], b1f[ni]);
                    mma_s8(accY[mi][ni], a1f[mi], b2f[ni]);
                    mma_s8(accY[mi][ni], a2f[mi], b1f[ni]);
                }
        }

        asm volatile("cp.async.wait_group 1;\n" ::);
        __syncthreads();
    }

    // epilogue: C = sA*sB*(255^2*X + 255*Y)/QMAX^2
    const float W1 = 65025.0f / (QMAX * QMAX);
    const float W2 = 255.0f / (QMAX * QMAX);
#pragma unroll
    for (int mi = 0; mi < 4; mi++) {
        int r0 = bm * 128 + wm * 64 + mi * 16 + (lane >> 2);
        float s0 = rmA[r0], s1 = rmA[r0 + 8];
#pragma unroll
        for (int ni = 0; ni < 4; ni++) {
            int c0 = bn * 128 + wn * 32 + ni * 8 + (lane & 3) * 2;
            float t0 = cmB[c0], t1 = cmB[c0 + 1];
            float v00 = s0 * t0 * ((float)accX[mi][ni][0] * W1 + (float)accY[mi][ni][0] * W2);
            float v01 = s0 * t1 * ((float)accX[mi][ni][1] * W1 + (float)accY[mi][ni][1] * W2);
            float v10 = s1 * t0 * ((float)accX[mi][ni][2] * W1 + (float)accY[mi][ni][2] * W2);
            float v11 = s1 * t1 * ((float)accX[mi][ni][3] * W1 + (float)accY[mi][ni][3] * W2);
            *(float2*)&C[(size_t)r0 * N + c0] = make_float2(v00, v01);
            *(float2*)&C[(size_t)(r0 + 8) * N + c0] = make_float2(v10, v11);
        }
    }
}

// ---------------------------------------------------------------------------
// RoPE + hi/lo split (reads fused qkv at head offset hoff)
// ---------------------------------------------------------------------------
__global__ void rope_split(const float* __restrict__ x, int xstride, int hoff,
                           const float* __restrict__ cosp, const float* __restrict__ sinp,
                           bf16* __restrict__ oh, bf16* __restrict__ ol,
                           int nheads, float scale) {
    int idx = blockIdx.x * blockDim.x + threadIdx.x;
    int total = B_ * T_ * nheads * 64;
    if (idx >= total) return;
    int d = idx & 63;
    int h = (idx >> 6) % nheads;
    int tok = idx / (64 * nheads);
    int t = tok & (T_ - 1);
    size_t ib = (size_t)tok * xstride + hoff + h * HD_;
    size_t ob = ((size_t)tok * nheads + h) * HD_;
    float c1 = cosp[t * HD_ + d], s1 = sinp[t * HD_ + d];
    float c2 = cosp[t * HD_ + d + 64], s2 = sinp[t * HD_ + d + 64];
    float x1 = x[ib + d], x2 = x[ib + d + 64];
    float y1 = (x1 * c1 - x2 * s1) * scale;
    float y2 = (x2 * c2 + x1 * s2) * scale;
    bf16 h1 = __float2bfloat16(y1);
    bf16 h2 = __float2bfloat16(y2);
    oh[ob + d] = h1;
    oh[ob + d + 64] = h2;
    ol[ob + d] = __float2bfloat16(y1 - __bfloat162float(h1));
    ol[ob + d + 64] = __float2bfloat16(y2 - __bfloat162float(h2));
}

// V slice of fused qkv (cols 2560..3071) -> dense hi/lo
__global__ void split_hl_v(const float* __restrict__ in, bf16* __restrict__ oh,
                           bf16* __restrict__ ol, int total) {
    int i = blockIdx.x * blockDim.x + threadIdx.x;
    if (i >= total) return;
    int tok = i >> 9, r = i & 511;
    float x = in[(size_t)tok * NQKV + 2560 + r];
    bf16 h = __float2bfloat16(x);
    oh[i] = h;
    ol[i] = __float2bfloat16(x - __bfloat162float(h));
}

// ---------------------------------------------------------------------------
// Tensor-core flash attention (R4 engine; epilogue now writes fp32 ctx)
// ---------------------------------------------------------------------------
#define FTILE (64 * 128 * 2)

__global__ __launch_bounds__(128) void flash_mma(const bf16* __restrict__ Qh,
                                                 const bf16* __restrict__ Ql,
                                                 const bf16* __restrict__ Kh,
                                                 const bf16* __restrict__ Kl,
                                                 const bf16* __restrict__ Vh,
                                                 const bf16* __restrict__ Vl,
                                                 float* __restrict__ ctx) {
    extern __shared__ char sm[];
    const uint32_t smBase = (uint32_t)__cvta_generic_to_shared(sm);
    const uint32_t sQh = smBase;
    const uint32_t sQl = smBase + FTILE;
    const uint32_t sKh = smBase + 2 * FTILE;
    const uint32_t sKl = smBase + 3 * FTILE;
    const uint32_t sVh = smBase + 4 * FTILE;
    const uint32_t sVl = smBase + 5 * FTILE;

    const int tid = threadIdx.x;
    const int warp = tid >> 5, lane = tid & 31;
    const int qtile = blockIdx.x;
    const int h = blockIdx.y;
    const int b = blockIdx.z;
    const int kvh = h / (NH_ / KVH_);
    const int q0 = qtile * 64;

    auto loadTile = [&](uint32_t sbase, const bf16* g, size_t gbase, int gstride) {
#pragma unroll
        for (int i = 0; i < 8; i++) {
            int q = tid + i * 128;
            int r = q >> 4, c = q & 15;
            int ch = (c & 8) | ((c ^ (r & 7)) & 7);
            cp16(sbase + r * 256 + (ch << 4), g + gbase + (size_t)r * gstride + c * 8);
        }
    };

    const size_t qgb = ((size_t)(b * T_ + q0) * NH_ + h) * HD_;
    loadTile(sQh, Qh, qgb, NH_ * HD_);
    loadTile(sQl, Ql, qgb, NH_ * HD_);
    cp_commit();

    float oAcc[16][4];
#pragma unroll
    for (int j = 0; j < 16; j++)
#pragma unroll
        for (int e = 0; e < 4; e++) oAcc[j][e] = 0.f;
    float mrow[2] = {-1e30f, -1e30f};
    float lrow[2] = {0.f, 0.f};

    for (int t0 = 0; t0 <= qtile; t0++) {
        const int s0 = t0 * 64;
        __syncthreads();
        const size_t kgb = ((size_t)(b * T_ + s0) * KVH_ + kvh) * HD_;
        loadTile(sKh, Kh, kgb, KVH_ * HD_);
        loadTile(sKl, Kl, kgb, KVH_ * HD_);
        loadTile(sVh, Vh, kgb, KVH_ * HD_);
        loadTile(sVl, Vl, kgb, KVH_ * HD_);
        cp_commit();
        asm volatile("cp.async.wait_group 0;\n" ::);
        __syncthreads();

        float sAcc[8][4];
#pragma unroll
        for (int j = 0; j < 8; j++)
#pragma unroll
            for (int e = 0; e < 4; e++) sAcc[j][e] = 0.f;

#pragma unroll
        for (int ks = 0; ks < 8; ks++) {
            int arow = warp * 16 + (lane & 15);
            int ac = ks * 2 + (lane >> 4);
            int ach = (ac & 8) | ((ac ^ (arow & 7)) & 7);
            uint32_t ah[4], al[4];
            ldsm4(ah, sQh + arow * 256 + (ach << 4));
            ldsm4(al, sQl + arow * 256 + (ach << 4));
            int krow_base = (lane & 7) + ((lane >> 4) & 1) * 8;
            int kc = ks * 2 + ((lane >> 3) & 1);
#pragma unroll
            for (int jp = 0; jp < 4; jp++) {
                int krow = jp * 16 + krow_base;
                int kch = (kc & 8) | ((kc ^ (krow & 7)) & 7);
                uint32_t bh4[4], bl4[4];
                ldsm4(bh4, sKh + krow * 256 + (kch << 4));
                ldsm4(bl4, sKl + krow * 256 + (kch << 4));
                mma16816(sAcc[jp * 2], ah, bh4);
                mma16816(sAcc[jp * 2], ah, bl4);
                mma16816(sAcc[jp * 2], al, bh4);
                mma16816(sAcc[jp * 2 + 1], ah, &bh4[2]);
                mma16816(sAcc[jp * 2 + 1], ah, &bl4[2]);
                mma16816(sAcc[jp * 2 + 1], al, &bh4[2]);
            }
        }

        if (t0 == qtile) {
            int r0 = warp * 16 + (lane >> 2);
#pragma unroll
            for (int j = 0; j < 8; j++) {
                int cb = j * 8 + (lane & 3) * 2;
                if (cb > r0) sAcc[j][0] = -1e30f;
                if (cb + 1 > r0) sAcc[j][1] = -1e30f;
                if (cb > r0 + 8) sAcc[j][2] = -1e30f;
                if (cb + 1 > r0 + 8) sAcc[j][3] = -1e30f;
            }
        }

        float mx0 = -1e30f, mx1 = -1e30f;
#pragma unroll
        for (int j = 0; j < 8; j++) {
            mx0 = fmaxf(mx0, fmaxf(sAcc[j][0], sAcc[j][1]));
            mx1 = fmaxf(mx1, fmaxf(sAcc[j][2], sAcc[j][3]));
        }
        mx0 = fmaxf(mx0, __shfl_xor_sync(0xffffffffu, mx0, 1));
        mx0 = fmaxf(mx0, __shfl_xor_sync(0xffffffffu, mx0, 2));
        mx1 = fmaxf(mx1, __shfl_xor_sync(0xffffffffu, mx1, 1));
        mx1 = fmaxf(mx1, __shfl_xor_sync(0xffffffffu, mx1, 2));
        float mn0 = fmaxf(mrow[0], mx0);
        float mn1 = fmaxf(mrow[1], mx1);
        float al0 = ex2(mrow[0] - mn0);
        float al1 = ex2(mrow[1] - mn1);
        mrow[0] = mn0;
        mrow[1] = mn1;
        float sum0 = 0.f, sum1 = 0.f;
#pragma unroll
        for (int j = 0; j < 8; j++) {
            sAcc[j][0] = ex2(sAcc[j][0] - mn0);
            sAcc[j][1] = ex2(sAcc[j][1] - mn0);
            sAcc[j][2] = ex2(sAcc[j][2] - mn1);
            sAcc[j][3] = ex2(sAcc[j][3] - mn1);
            sum0 += sAcc[j][0] + sAcc[j][1];
            sum1 += sAcc[j][2] + sAcc[j][3];
        }
        sum0 += __shfl_xor_sync(0xffffffffu, sum0, 1);
        sum0 += __shfl_xor_sync(0xffffffffu, sum0, 2);
        sum1 += __shfl_xor_sync(0xffffffffu, sum1, 1);
        sum1 += __shfl_xor_sync(0xffffffffu, sum1, 2);
        lrow[0] = lrow[0] * al0 + sum0;
        lrow[1] = lrow[1] * al1 + sum1;
#pragma unroll
        for (int j = 0; j < 16; j++) {
            oAcc[j][0] *= al0;
            oAcc[j][1] *= al0;
            oAcc[j][2] *= al1;
            oAcc[j][3] *= al1;
        }

        int vrow_b = (lane & 15);
        int vcb = (lane >> 4);
#pragma unroll
        for (int kt = 0; kt < 4; kt++) {
            uint32_t ph[4], pl[4];
            {
                float p0 = sAcc[2 * kt][0], p1 = sAcc[2 * kt][1];
                float p2 = sAcc[2 * kt][2], p3 = sAcc[2 * kt][3];
                float p4 = sAcc[2 * kt + 1][0], p5 = sAcc[2 * kt + 1][1];
                float p6 = sAcc[2 * kt + 1][2], p7 = sAcc[2 * kt + 1][3];
                float h0 = __bfloat162float(__float2bfloat16(p0));
                float h1 = __bfloat162float(__float2bfloat16(p1));
                float h2 = __bfloat162float(__float2bfloat16(p2));
                float h3 = __bfloat162float(__float2bfloat16(p3));
                float h4 = __bfloat162float(__float2bfloat16(p4));
                float h5 = __bfloat162float(__float2bfloat16(p5));
                float h6 = __bfloat162float(__float2bfloat16(p6));
                float h7 = __bfloat162float(__float2bfloat16(p7));
                ph[0] = packbf2(h0, h1); ph[1] = packbf2(h2, h3);
                ph[2] = packbf2(h4, h5); ph[3] = packbf2(h6, h7);
                pl[0] = packbf2(p0 - h0, p1 - h1); pl[1] = packbf2(p2 - h2, p3 - h3);
                pl[2] = packbf2(p4 - h4, p5 - h5); pl[3] = packbf2(p6 - h6, p7 - h7);
            }
            int vrow = kt * 16 + vrow_b;
#pragma unroll
            for (int jp2 = 0; jp2 < 8; jp2++) {
                int vc = jp2 * 2 + vcb;
                int vch = (vc & 8) | ((vc ^ (vrow & 7)) & 7);
                uint32_t vh4[4], vl4[4];
                ldsm4t(vh4, sVh + vrow * 256 + (vch << 4));
                ldsm4t(vl4, sVl + vrow * 256 + (vch << 4));
                mma16816(oAcc[jp2 * 2], ph, vh4);
                mma16816(oAcc[jp2 * 2], ph, vl4);
                mma16816(oAcc[jp2 * 2], pl, vh4);
                mma16816(oAcc[jp2 * 2 + 1], ph, &vh4[2]);
                mma16816(oAcc[jp2 * 2 + 1], ph, &vl4[2]);
                mma16816(oAcc[jp2 * 2 + 1], pl, &vh4[2]);
            }
        }
    }

    // epilogue: normalize, write fp32 ctx (b,t,h,d)
    float inv0 = 1.f / lrow[0];
    float inv1 = 1.f / lrow[1];
    int r0 = q0 + warp * 16 + (lane >> 2);
    size_t row0 = (size_t)(b * T_ + r0) * HID_;
    size_t row1 = row0 + (size_t)8 * HID_;
#pragma unroll
    for (int j = 0; j < 16; j++) {
        int col = h * HD_ + j * 8 + (lane & 3) * 2;
        *(float2*)&ctx[row0 + col] = make_float2(oAcc[j][0] * inv0, oAcc[j][1] * inv0);
        *(float2*)&ctx[row1 + col] = make_float2(oAcc[j][2] * inv1, oAcc[j][3] * inv1);
    }
}

// ---------------------------------------------------------------------------
// Launch
// ---------------------------------------------------------------------------
extern "C" void kernel_launch(void* const* d_in, const int* in_sizes, int n_in,
                              void* d_out, int out_size) {
    const float* hidden = (const float*)d_in[0];
    const float* cosp = (const float*)d_in[2];
    const float* sinp = (const float*)d_in[3];
    const float* Wq = (const float*)d_in[4];
    const float* Wk = (const float*)d_in[5];
    const float* Wv = (const float*)d_in[6];
    const float* Wo = (const float*)d_in[7];
    float* out = (float*)d_out;

    float *qkv, *ctx, *rm_hid, *rm_ctx, *cm_qkv, *cm_wo;
    signed char *a_hid, *a_ctx, *bt_qkv, *bt_wo;
    bf16 *qh, *ql, *kh, *kl, *vh, *vl;
    cudaGetSymbolAddress((void**)&qkv, g_qkv);
    cudaGetSymbolAddress((void**)&ctx, g_ctx);
    cudaGetSymbolAddress((void**)&rm_hid, g_rm_hid);
    cudaGetSymbolAddress((void**)&rm_ctx, g_rm_ctx);
    cudaGetSymbolAddress((void**)&cm_qkv, g_cm_qkv);
    cudaGetSymbolAddress((void**)&cm_wo, g_cm_wo);
    cudaGetSymbolAddress((void**)&a_hid, g_a_hid);
    cudaGetSymbolAddress((void**)&a_ctx, g_a_ctx);
    cudaGetSymbolAddress((void**)&bt_qkv, g_bt_qkv);
    cudaGetSymbolAddress((void**)&bt_wo, g_bt_wo);
    cudaGetSymbolAddress((void**)&qh, g_qh);
    cudaGetSymbolAddress((void**)&ql, g_ql);
    cudaGetSymbolAddress((void**)&kh, g_kh);
    cudaGetSymbolAddress((void**)&kl, g_kl);
    cudaGetSymbolAddress((void**)&vh, g_vh);
    cudaGetSymbolAddress((void**)&vl, g_vl);

    const int M = B_ * T_;  // 4096

    constexpr int GEMM_SMEM = 3 * IST;  // 96 KB
    cudaFuncSetAttribute(i8gemm, cudaFuncAttributeMaxDynamicSharedMemorySize, GEMM_SMEM);
    cudaFuncSetAttribute(flash_mma, cudaFuncAttributeMaxDynamicSharedMemorySize, 6 * FTILE);

    // scales
    rowmax_kernel<<<M, 256>>>(hidden, rm_hid, KDIM);
    colmax_kernel<<<(2048 + 255) / 256, 256>>>(Wq, cm_qkv, KDIM, 2048);
    colmax_kernel<<<(512 + 255) / 256, 256>>>(Wk, cm_qkv + 2048, KDIM, 512);
    colmax_kernel<<<(512 + 255) / 256, 256>>>(Wv, cm_qkv + 2560, KDIM, 512);
    colmax_kernel<<<(2048 + 255) / 256, 256>>>(Wo, cm_wo, KDIM, 2048);

    // quantize
    quantA_kernel<<<(M * KDIM / 4 + 255) / 256, 256>>>(hidden, rm_hid, a_hid, M, KDIM);
    quantBt_kernel<<<dim3(2048 / 32, KDIM / 32), dim3(32, 8)>>>(Wq, cm_qkv, bt_qkv, KDIM, 2048, 0);
    quantBt_kernel<<<dim3(512 / 32, KDIM / 32), dim3(32, 8)>>>(Wk, cm_qkv, bt_qkv, KDIM, 512, 2048);
    quantBt_kernel<<<dim3(512 / 32, KDIM / 32), dim3(32, 8)>>>(Wv, cm_qkv, bt_qkv, KDIM, 512, 2560);
    quantBt_kernel<<<dim3(2048 / 32, KDIM / 32), dim3(32, 8)>>>(Wo, cm_wo, bt_wo, KDIM, 2048, 0);

    // fused QKV projection (int8 2-limb)
    i8gemm<<<dim3(NQKV / 128, M / 128), 256, GEMM_SMEM>>>(a_hid, bt_qkv, qkv,
                                                          rm_hid, cm_qkv, M, NQKV, KDIM);

    // RoPE + hi/lo splits
    const float qscale = 1.4426950408889634f * 0.08838834764831845f;
    rope_split<<<(B_ * T_ * NH_ * 64 + 255) / 256, 256>>>(qkv, NQKV, 0, cosp, sinp, qh, ql, NH_, qscale);
    rope_split<<<(B_ * T_ * KVH_ * 64 + 255) / 256, 256>>>(qkv, NQKV, 2048, cosp, sinp, kh, kl, KVH_, 1.0f);
    split_hl_v<<<(M * 512 + 255) / 256, 256>>>(qkv, vh, vl, M * 512);

    // flash attention -> fp32 ctx
    flash_mma<<<dim3(T_ / 64, NH_, B_), 128, 6 * FTILE>>>(qh, ql, kh, kl, vh, vl, ctx);

    // quantize ctx, output projection
    rowmax_kernel<<<M, 256>>>(ctx, rm_ctx, KDIM);
    quantA_kernel<<<(M * KDIM / 4 + 255) / 256, 256>>>(ctx, rm_ctx, a_ctx, M, KDIM);
    i8gemm<<<dim3(2048 / 128, M / 128), 256, GEMM_SMEM>>>(a_ctx, bt_wo, out,
                                                          rm_ctx, cm_wo, M, 2048, KDIM);
}

// round 9
// speedup vs baseline: 4.6838x; 4.6838x over previous
#include <cuda_runtime.h>
#include <cuda_bf16.h>
#include <cuda_fp16.h>
#include <cstdint>

#define B_ 2
#define T_ 2048
#define HID_ 2048
#define NH_ 16
#define KVH_ 4
#define HD_ 128
#define NQKV 3072
#define KDIM 2048

typedef __nv_bfloat16 bf16;

// fp32 QKV GEMM output
__device__ float g_qkv[(size_t)B_ * T_ * NQKV];
// fp16 GEMM operands
__device__ __half g_hid_h[(size_t)4096 * KDIM];
__device__ __half g_wqkv_h[(size_t)KDIM * NQKV];
__device__ __half g_wo_h[(size_t)KDIM * HID_];
__device__ __half g_ctx_h[(size_t)4096 * HID_];   // written by flash epilogue
// flash hi/lo inputs (bf16 split — high precision attention)
__device__ bf16 g_qh[(size_t)B_ * T_ * NH_ * HD_];
__device__ bf16 g_ql[(size_t)B_ * T_ * NH_ * HD_];
__device__ bf16 g_kh[(size_t)B_ * T_ * KVH_ * HD_];
__device__ bf16 g_kl[(size_t)B_ * T_ * KVH_ * HD_];
__device__ bf16 g_vh[(size_t)B_ * T_ * KVH_ * HD_];
__device__ bf16 g_vl[(size_t)B_ * T_ * KVH_ * HD_];

// ---------------------------------------------------------------------------
// helpers
// ---------------------------------------------------------------------------
__device__ __forceinline__ void cp16(uint32_t s, const void* g) {
    asm volatile("cp.async.cg.shared.global [%0], [%1], 16;\n" :: "r"(s), "l"(g));
}
__device__ __forceinline__ void cp_commit() {
    asm volatile("cp.async.commit_group;\n" ::);
}
__device__ __forceinline__ void mma_f16(float* c, const uint32_t* a, const uint32_t* b) {
    asm volatile(
        "mma.sync.aligned.m16n8k16.row.col.f32.f16.f16.f32 "
        "{%0,%1,%2,%3}, {%4,%5,%6,%7}, {%8,%9}, {%0,%1,%2,%3};\n"
        : "+f"(c[0]), "+f"(c[1]), "+f"(c[2]), "+f"(c[3])
        : "r"(a[0]), "r"(a[1]), "r"(a[2]), "r"(a[3]), "r"(b[0]), "r"(b[1]));
}
__device__ __forceinline__ void mma_bf16(float* c, const uint32_t* a, const uint32_t* b) {
    asm volatile(
        "mma.sync.aligned.m16n8k16.row.col.f32.bf16.bf16.f32 "
        "{%0,%1,%2,%3}, {%4,%5,%6,%7}, {%8,%9}, {%0,%1,%2,%3};\n"
        : "+f"(c[0]), "+f"(c[1]), "+f"(c[2]), "+f"(c[3])
        : "r"(a[0]), "r"(a[1]), "r"(a[2]), "r"(a[3]), "r"(b[0]), "r"(b[1]));
}
__device__ __forceinline__ void ldsm4(uint32_t* d, uint32_t addr) {
    asm volatile("ldmatrix.sync.aligned.m8n8.x4.shared.b16 {%0,%1,%2,%3}, [%4];\n"
                 : "=r"(d[0]), "=r"(d[1]), "=r"(d[2]), "=r"(d[3]) : "r"(addr));
}
__device__ __forceinline__ void ldsm4t(uint32_t* d, uint32_t addr) {
    asm volatile("ldmatrix.sync.aligned.m8n8.x4.trans.shared.b16 {%0,%1,%2,%3}, [%4];\n"
                 : "=r"(d[0]), "=r"(d[1]), "=r"(d[2]), "=r"(d[3]) : "r"(addr));
}
__device__ __forceinline__ float ex2(float x) {
    float r;
    asm("ex2.approx.f32 %0, %1;" : "=f"(r) : "f"(x));
    return r;
}
__device__ __forceinline__ uint32_t packbf2(float a, float b) {
    __nv_bfloat162 t = __floats2bfloat162_rn(a, b);
    return *(uint32_t*)&t;
}

// ---------------------------------------------------------------------------
// fp32 -> fp16 converts
// ---------------------------------------------------------------------------
// dense: 8 elems/thread
__global__ void cvt_f16(const float* __restrict__ in, __half* __restrict__ out,
                        int total8) {
    int i = blockIdx.x * blockDim.x + threadIdx.x;
    if (i >= total8) return;
    float4 x0 = *(const float4*)(in + (size_t)i * 8);
    float4 x1 = *(const float4*)(in + (size_t)i * 8 + 4);
    __half2 h[4];
    h[0] = __floats2half2_rn(x0.x, x0.y);
    h[1] = __floats2half2_rn(x0.z, x0.w);
    h[2] = __floats2half2_rn(x1.x, x1.y);
    h[3] = __floats2half2_rn(x1.z, x1.w);
    *(uint4*)(out + (size_t)i * 8) = *(uint4*)h;
}
// W [K][N] -> out [K][NO] at column offset noff (coalesced both sides)
__global__ void cvt_f16_off(const float* __restrict__ W, __half* __restrict__ out,
                            int K, int N, int NO, int noff) {
    int i = blockIdx.x * blockDim.x + threadIdx.x;
    if (i >= K * N) return;
    int k = i / N, n = i - k * N;
    out[(size_t)k * NO + noff + n] = __float2half(W[i]);
}

// ---------------------------------------------------------------------------
// fp16 GEMM (R4-proven config): C(M,N) fp32 = A(M,K) @ B(K,N), fp16 inputs.
// 128x128x64 tile, 3-stage cp.async, 256 threads, warp tile 64x32.
// ---------------------------------------------------------------------------
#define GBM 128
#define GBN 128
#define GBK 64
#define GSTAGES 3
#define A_STAGE_BYTES (GBM * GBK * 2)
#define B_STAGE_BYTES (GBK * GBN * 2)

__global__ __launch_bounds__(256) void f16gemm(const __half* __restrict__ A,
                                               const __half* __restrict__ B,
                                               float* __restrict__ C,
                                               int M, int N, int K) {
    extern __shared__ char sm[];
    const uint32_t smBase = (uint32_t)__cvta_generic_to_shared(sm);
    const uint32_t aBase = smBase;
    const uint32_t bBase = smBase + GSTAGES * A_STAGE_BYTES;

    const int tid = threadIdx.x;
    const int bm = blockIdx.y, bn = blockIdx.x;
    const int warp = tid >> 5, lane = tid & 31;
    const int wm = warp >> 2;
    const int wn = warp & 3;

    float acc[4][4][4];
#pragma unroll
    for (int mi = 0; mi < 4; mi++)
#pragma unroll
        for (int ni = 0; ni < 4; ni++)
#pragma unroll
            for (int e = 0; e < 4; e++) acc[mi][ni][e] = 0.f;

    const int KT = K / GBK;

    auto load_stage = [&](int sidx, int kt) {
#pragma unroll
        for (int i = 0; i < 4; i++) {
            int q = tid + i * 256;
            int r = q >> 3, c = q & 7;
            const __half* g = A + (size_t)(bm * GBM + r) * K + kt * GBK + c * 8;
            uint32_t s = aBase + sidx * A_STAGE_BYTES + r * 128 + (((c ^ (r & 7)) & 7) << 4);
            cp16(s, g);
        }
#pragma unroll
        for (int i = 0; i < 4; i++) {
            int q = tid + i * 256;
            int r = q >> 4, c = q & 15;
            const __half* g = B + (size_t)(kt * GBK + r) * N + bn * GBN + c * 8;
            int ch = (c & 8) | ((c ^ (r & 7)) & 7);
            uint32_t s = bBase + sidx * B_STAGE_BYTES + r * 256 + (ch << 4);
            cp16(s, g);
        }
    };

#pragma unroll
    for (int s = 0; s < GSTAGES - 1; s++) {
        load_stage(s, s);
        cp_commit();
    }
    asm volatile("cp.async.wait_group %0;\n" :: "n"(GSTAGES - 2));
    __syncthreads();

    const int a_row = wm * 64 + (lane & 15);
    const int a_col8 = (lane >> 4) * 8;
    const int b_row = (lane & 15);
    const int b_colb = wn * 32 + (lane >> 4) * 8;

    for (int kt = 0; kt < KT; kt++) {
        const int cur = kt % GSTAGES;
        if (kt + GSTAGES - 1 < KT) load_stage((kt + GSTAGES - 1) % GSTAGES, kt + GSTAGES - 1);
        cp_commit();

        const uint32_t aS = aBase + cur * A_STAGE_BYTES;
        const uint32_t bS = bBase + cur * B_STAGE_BYTES;

#pragma unroll
        for (int ks = 0; ks < GBK / 16; ks++) {
            uint32_t af[4][4];
#pragma unroll
            for (int mi = 0; mi < 4; mi++) {
                int row = a_row + mi * 16;
                int col = ks * 16 + a_col8;
                uint32_t addr = aS + row * 128 + ((((col >> 3) ^ (row & 7)) & 7) << 4);
                ldsm4(af[mi], addr);
            }
            uint32_t bfr[4][2];
#pragma unroll
            for (int np = 0; np < 2; np++) {
                int row = ks * 16 + b_row;
                int col = b_colb + np * 16;
                int ch = (col >> 3);
                ch = (ch & 8) | ((ch ^ (row & 7)) & 7);
                uint32_t addr = bS + row * 256 + (ch << 4);
                uint32_t tmp[4];
                ldsm4t(tmp, addr);
                bfr[np * 2][0] = tmp[0]; bfr[np * 2][1] = tmp[1];
                bfr[np * 2 + 1][0] = tmp[2]; bfr[np * 2 + 1][1] = tmp[3];
            }
#pragma unroll
            for (int mi = 0; mi < 4; mi++)
#pragma unroll
                for (int ni = 0; ni < 4; ni++)
                    mma_f16(acc[mi][ni], af[mi], bfr[ni]);
        }

        asm volatile("cp.async.wait_group %0;\n" :: "n"(GSTAGES - 2));
        __syncthreads();
    }

#pragma unroll
    for (int mi = 0; mi < 4; mi++) {
#pragma unroll
        for (int ni = 0; ni < 4; ni++) {
            int row = bm * GBM + wm * 64 + mi * 16 + (lane >> 2);
            int col = bn * GBN + wn * 32 + ni * 8 + (lane & 3) * 2;
            *(float2*)&C[(size_t)row * N + col] = make_float2(acc[mi][ni][0], acc[mi][ni][1]);
            *(float2*)&C[(size_t)(row + 8) * N + col] = make_float2(acc[mi][ni][2], acc[mi][ni][3]);
        }
    }
}

// ---------------------------------------------------------------------------
// RoPE + bf16 hi/lo split (reads fused fp32 qkv at head offset hoff)
// ---------------------------------------------------------------------------
__global__ void rope_split(const float* __restrict__ x, int xstride, int hoff,
                           const float* __restrict__ cosp, const float* __restrict__ sinp,
                           bf16* __restrict__ oh, bf16* __restrict__ ol,
                           int nheads, float scale) {
    int idx = blockIdx.x * blockDim.x + threadIdx.x;
    int total = B_ * T_ * nheads * 64;
    if (idx >= total) return;
    int d = idx & 63;
    int h = (idx >> 6) % nheads;
    int tok = idx / (64 * nheads);
    int t = tok & (T_ - 1);
    size_t ib = (size_t)tok * xstride + hoff + h * HD_;
    size_t ob = ((size_t)tok * nheads + h) * HD_;
    float c1 = cosp[t * HD_ + d], s1 = sinp[t * HD_ + d];
    float c2 = cosp[t * HD_ + d + 64], s2 = sinp[t * HD_ + d + 64];
    float x1 = x[ib + d], x2 = x[ib + d + 64];
    float y1 = (x1 * c1 - x2 * s1) * scale;
    float y2 = (x2 * c2 + x1 * s2) * scale;
    bf16 h1 = __float2bfloat16(y1);
    bf16 h2 = __float2bfloat16(y2);
    oh[ob + d] = h1;
    oh[ob + d + 64] = h2;
    ol[ob + d] = __float2bfloat16(y1 - __bfloat162float(h1));
    ol[ob + d + 64] = __float2bfloat16(y2 - __bfloat162float(h2));
}

// V slice of fused qkv (cols 2560..3071) -> dense hi/lo
__global__ void split_hl_v(const float* __restrict__ in, bf16* __restrict__ oh,
                           bf16* __restrict__ ol, int total) {
    int i = blockIdx.x * blockDim.x + threadIdx.x;
    if (i >= total) return;
    int tok = i >> 9, r = i & 511;
    float x = in[(size_t)tok * NQKV + 2560 + r];
    bf16 h = __float2bfloat16(x);
    oh[i] = h;
    ol[i] = __float2bfloat16(x - __bfloat162float(h));
}

// ---------------------------------------------------------------------------
// Tensor-core flash attention (R4 engine; epilogue writes fp16 ctx)
// ---------------------------------------------------------------------------
#define FTILE (64 * 128 * 2)

__global__ __launch_bounds__(128) void flash_mma(const bf16* __restrict__ Qh,
                                                 const bf16* __restrict__ Ql,
                                                 const bf16* __restrict__ Kh,
                                                 const bf16* __restrict__ Kl,
                                                 const bf16* __restrict__ Vh,
                                                 const bf16* __restrict__ Vl,
                                                 __half* __restrict__ ctxH) {
    extern __shared__ char sm[];
    const uint32_t smBase = (uint32_t)__cvta_generic_to_shared(sm);
    const uint32_t sQh = smBase;
    const uint32_t sQl = smBase + FTILE;
    const uint32_t sKh = smBase + 2 * FTILE;
    const uint32_t sKl = smBase + 3 * FTILE;
    const uint32_t sVh = smBase + 4 * FTILE;
    const uint32_t sVl = smBase + 5 * FTILE;

    const int tid = threadIdx.x;
    const int warp = tid >> 5, lane = tid & 31;
    const int qtile = blockIdx.x;
    const int h = blockIdx.y;
    const int b = blockIdx.z;
    const int kvh = h / (NH_ / KVH_);
    const int q0 = qtile * 64;

    auto loadTile = [&](uint32_t sbase, const bf16* g, size_t gbase, int gstride) {
#pragma unroll
        for (int i = 0; i < 8; i++) {
            int q = tid + i * 128;
            int r = q >> 4, c = q & 15;
            int ch = (c & 8) | ((c ^ (r & 7)) & 7);
            cp16(sbase + r * 256 + (ch << 4), g + gbase + (size_t)r * gstride + c * 8);
        }
    };

    const size_t qgb = ((size_t)(b * T_ + q0) * NH_ + h) * HD_;
    loadTile(sQh, Qh, qgb, NH_ * HD_);
    loadTile(sQl, Ql, qgb, NH_ * HD_);
    cp_commit();

    float oAcc[16][4];
#pragma unroll
    for (int j = 0; j < 16; j++)
#pragma unroll
        for (int e = 0; e < 4; e++) oAcc[j][e] = 0.f;
    float mrow[2] = {-1e30f, -1e30f};
    float lrow[2] = {0.f, 0.f};

    for (int t0 = 0; t0 <= qtile; t0++) {
        const int s0 = t0 * 64;
        __syncthreads();
        const size_t kgb = ((size_t)(b * T_ + s0) * KVH_ + kvh) * HD_;
        loadTile(sKh, Kh, kgb, KVH_ * HD_);
        loadTile(sKl, Kl, kgb, KVH_ * HD_);
        loadTile(sVh, Vh, kgb, KVH_ * HD_);
        loadTile(sVl, Vl, kgb, KVH_ * HD_);
        cp_commit();
        asm volatile("cp.async.wait_group 0;\n" ::);
        __syncthreads();

        float sAcc[8][4];
#pragma unroll
        for (int j = 0; j < 8; j++)
#pragma unroll
            for (int e = 0; e < 4; e++) sAcc[j][e] = 0.f;

#pragma unroll
        for (int ks = 0; ks < 8; ks++) {
            int arow = warp * 16 + (lane & 15);
            int ac = ks * 2 + (lane >> 4);
            int ach = (ac & 8) | ((ac ^ (arow & 7)) & 7);
            uint32_t ah[4], al[4];
            ldsm4(ah, sQh + arow * 256 + (ach << 4));
            ldsm4(al, sQl + arow * 256 + (ach << 4));
            int krow_base = (lane & 7) + ((lane >> 4) & 1) * 8;
            int kc = ks * 2 + ((lane >> 3) & 1);
#pragma unroll
            for (int jp = 0; jp < 4; jp++) {
                int krow = jp * 16 + krow_base;
                int kch = (kc & 8) | ((kc ^ (krow & 7)) & 7);
                uint32_t bh4[4], bl4[4];
                ldsm4(bh4, sKh + krow * 256 + (kch << 4));
                ldsm4(bl4, sKl + krow * 256 + (kch << 4));
                mma_bf16(sAcc[jp * 2], ah, bh4);
                mma_bf16(sAcc[jp * 2], ah, bl4);
                mma_bf16(sAcc[jp * 2], al, bh4);
                mma_bf16(sAcc[jp * 2 + 1], ah, &bh4[2]);
                mma_bf16(sAcc[jp * 2 + 1], ah, &bl4[2]);
                mma_bf16(sAcc[jp * 2 + 1], al, &bh4[2]);
            }
        }

        if (t0 == qtile) {
            int r0 = warp * 16 + (lane >> 2);
#pragma unroll
            for (int j = 0; j < 8; j++) {
                int cb = j * 8 + (lane & 3) * 2;
                if (cb > r0) sAcc[j][0] = -1e30f;
                if (cb + 1 > r0) sAcc[j][1] = -1e30f;
                if (cb > r0 + 8) sAcc[j][2] = -1e30f;
                if (cb + 1 > r0 + 8) sAcc[j][3] = -1e30f;
            }
        }

        float mx0 = -1e30f, mx1 = -1e30f;
#pragma unroll
        for (int j = 0; j < 8; j++) {
            mx0 = fmaxf(mx0, fmaxf(sAcc[j][0], sAcc[j][1]));
            mx1 = fmaxf(mx1, fmaxf(sAcc[j][2], sAcc[j][3]));
        }
        mx0 = fmaxf(mx0, __shfl_xor_sync(0xffffffffu, mx0, 1));
        mx0 = fmaxf(mx0, __shfl_xor_sync(0xffffffffu, mx0, 2));
        mx1 = fmaxf(mx1, __shfl_xor_sync(0xffffffffu, mx1, 1));
        mx1 = fmaxf(mx1, __shfl_xor_sync(0xffffffffu, mx1, 2));
        float mn0 = fmaxf(mrow[0], mx0);
        float mn1 = fmaxf(mrow[1], mx1);
        float al0 = ex2(mrow[0] - mn0);
        float al1 = ex2(mrow[1] - mn1);
        mrow[0] = mn0;
        mrow[1] = mn1;
        float sum0 = 0.f, sum1 = 0.f;
#pragma unroll
        for (int j = 0; j < 8; j++) {
            sAcc[j][0] = ex2(sAcc[j][0] - mn0);
            sAcc[j][1] = ex2(sAcc[j][1] - mn0);
            sAcc[j][2] = ex2(sAcc[j][2] - mn1);
            sAcc[j][3] = ex2(sAcc[j][3] - mn1);
            sum0 += sAcc[j][0] + sAcc[j][1];
            sum1 += sAcc[j][2] + sAcc[j][3];
        }
        sum0 += __shfl_xor_sync(0xffffffffu, sum0, 1);
        sum0 += __shfl_xor_sync(0xffffffffu, sum0, 2);
        sum1 += __shfl_xor_sync(0xffffffffu, sum1, 1);
        sum1 += __shfl_xor_sync(0xffffffffu, sum1, 2);
        lrow[0] = lrow[0] * al0 + sum0;
        lrow[1] = lrow[1] * al1 + sum1;
#pragma unroll
        for (int j = 0; j < 16; j++) {
            oAcc[j][0] *= al0;
            oAcc[j][1] *= al0;
            oAcc[j][2] *= al1;
            oAcc[j][3] *= al1;
        }

        int vrow_b = (lane & 15);
        int vcb = (lane >> 4);
#pragma unroll
        for (int kt = 0; kt < 4; kt++) {
            uint32_t ph[4], pl[4];
            {
                float p0 = sAcc[2 * kt][0], p1 = sAcc[2 * kt][1];
                float p2 = sAcc[2 * kt][2], p3 = sAcc[2 * kt][3];
                float p4 = sAcc[2 * kt + 1][0], p5 = sAcc[2 * kt + 1][1];
                float p6 = sAcc[2 * kt + 1][2], p7 = sAcc[2 * kt + 1][3];
                float h0 = __bfloat162float(__float2bfloat16(p0));
                float h1 = __bfloat162float(__float2bfloat16(p1));
                float h2 = __bfloat162float(__float2bfloat16(p2));
                float h3 = __bfloat162float(__float2bfloat16(p3));
                float h4 = __bfloat162float(__float2bfloat16(p4));
                float h5 = __bfloat162float(__float2bfloat16(p5));
                float h6 = __bfloat162float(__float2bfloat16(p6));
                float h7 = __bfloat162float(__float2bfloat16(p7));
                ph[0] = packbf2(h0, h1); ph[1] = packbf2(h2, h3);
                ph[2] = packbf2(h4, h5); ph[3] = packbf2(h6, h7);
                pl[0] = packbf2(p0 - h0, p1 - h1); pl[1] = packbf2(p2 - h2, p3 - h3);
                pl[2] = packbf2(p4 - h4, p5 - h5); pl[3] = packbf2(p6 - h6, p7 - h7);
            }
            int vrow = kt * 16 + vrow_b;
#pragma unroll
            for (int jp2 = 0; jp2 < 8; jp2++) {
                int vc = jp2 * 2 + vcb;
                int vch = (vc & 8) | ((vc ^ (vrow & 7)) & 7);
                uint32_t vh4[4], vl4[4];
                ldsm4t(vh4, sVh + vrow * 256 + (vch << 4));
                ldsm4t(vl4, sVl + vrow * 256 + (vch << 4));
                mma_bf16(oAcc[jp2 * 2], ph, vh4);
                mma_bf16(oAcc[jp2 * 2], ph, vl4);
                mma_bf16(oAcc[jp2 * 2], pl, vh4);
                mma_bf16(oAcc[jp2 * 2 + 1], ph, &vh4[2]);
                mma_bf16(oAcc[jp2 * 2 + 1], ph, &vl4[2]);
                mma_bf16(oAcc[jp2 * 2 + 1], pl, &vh4[2]);
            }
        }
    }

    // epilogue: normalize, write fp16 ctx (b,t,h,d) — direct A operand for O-GEMM
    float inv0 = 1.f / lrow[0];
    float inv1 = 1.f / lrow[1];
    int r0 = q0 + warp * 16 + (lane >> 2);
    size_t row0 = (size_t)(b * T_ + r0) * HID_;
    size_t row1 = row0 + (size_t)8 * HID_;
#pragma unroll
    for (int j = 0; j < 16; j++) {
        int col = h * HD_ + j * 8 + (lane & 3) * 2;
        __half2 v01 = __floats2half2_rn(oAcc[j][0] * inv0, oAcc[j][1] * inv0);
        __half2 v23 = __floats2half2_rn(oAcc[j][2] * inv1, oAcc[j][3] * inv1);
        *(uint32_t*)(ctxH + row0 + col) = *(uint32_t*)&v01;
        *(uint32_t*)(ctxH + row1 + col) = *(uint32_t*)&v23;
    }
}

// ---------------------------------------------------------------------------
// Launch
// ---------------------------------------------------------------------------
extern "C" void kernel_launch(void* const* d_in, const int* in_sizes, int n_in,
                              void* d_out, int out_size) {
    const float* hidden = (const float*)d_in[0];
    const float* cosp = (const float*)d_in[2];
    const float* sinp = (const float*)d_in[3];
    const float* Wq = (const float*)d_in[4];
    const float* Wk = (const float*)d_in[5];
    const float* Wv = (const float*)d_in[6];
    const float* Wo = (const float*)d_in[7];
    float* out = (float*)d_out;

    float* qkv;
    __half *hid_h, *wqkv_h, *wo_h, *ctx_h;
    bf16 *qh, *ql, *kh, *kl, *vh, *vl;
    cudaGetSymbolAddress((void**)&qkv, g_qkv);
    cudaGetSymbolAddress((void**)&hid_h, g_hid_h);
    cudaGetSymbolAddress((void**)&wqkv_h, g_wqkv_h);
    cudaGetSymbolAddress((void**)&wo_h, g_wo_h);
    cudaGetSymbolAddress((void**)&ctx_h, g_ctx_h);
    cudaGetSymbolAddress((void**)&qh, g_qh);
    cudaGetSymbolAddress((void**)&ql, g_ql);
    cudaGetSymbolAddress((void**)&kh, g_kh);
    cudaGetSymbolAddress((void**)&kl, g_kl);
    cudaGetSymbolAddress((void**)&vh, g_vh);
    cudaGetSymbolAddress((void**)&vl, g_vl);

    const int M = B_ * T_;  // 4096

    constexpr int GEMM_SMEM = GSTAGES * (A_STAGE_BYTES + B_STAGE_BYTES);  // 96 KB
    cudaFuncSetAttribute(f16gemm, cudaFuncAttributeMaxDynamicSharedMemorySize, GEMM_SMEM);
    cudaFuncSetAttribute(flash_mma, cudaFuncAttributeMaxDynamicSharedMemorySize, 6 * FTILE);

    // fp32 -> fp16 converts
    cvt_f16<<<(M * KDIM / 8 + 255) / 256, 256>>>(hidden, hid_h, M * KDIM / 8);
    cvt_f16_off<<<(KDIM * 2048 + 255) / 256, 256>>>(Wq, wqkv_h, KDIM, 2048, NQKV, 0);
    cvt_f16_off<<<(KDIM * 512 + 255) / 256, 256>>>(Wk, wqkv_h, KDIM, 512, NQKV, 2048);
    cvt_f16_off<<<(KDIM * 512 + 255) / 256, 256>>>(Wv, wqkv_h, KDIM, 512, NQKV, 2560);
    cvt_f16_off<<<(KDIM * 2048 + 255) / 256, 256>>>(Wo, wo_h, KDIM, 2048, 2048, 0);

    // fused QKV projection (fp16, real K=2048)
    f16gemm<<<dim3(NQKV / GBN, M / GBM), 256, GEMM_SMEM>>>(hid_h, wqkv_h, qkv, M, NQKV, KDIM);

    // RoPE + bf16 hi/lo splits (high-precision attention inputs)
    const float qscale = 1.4426950408889634f * 0.08838834764831845f;
    rope_split<<<(B_ * T_ * NH_ * 64 + 255) / 256, 256>>>(qkv, NQKV, 0, cosp, sinp, qh, ql, NH_, qscale);
    rope_split<<<(B_ * T_ * KVH_ * 64 + 255) / 256, 256>>>(qkv, NQKV, 2048, cosp, sinp, kh, kl, KVH_, 1.0f);
    split_hl_v<<<(M * 512 + 255) / 256, 256>>>(qkv, vh, vl, M * 512);

    // flash attention -> fp16 ctx
    flash_mma<<<dim3(T_ / 64, NH_, B_), 128, 6 * FTILE>>>(qh, ql, kh, kl, vh, vl, ctx_h);

    // output projection (fp16, real K=2048)
    f16gemm<<<dim3(2048 / GBN, M / GBM), 256, GEMM_SMEM>>>(ctx_h, wo_h, out, M, 2048, KDIM);
}

// round 10
// speedup vs baseline: 6.5754x; 1.4039x over previous
#include <cuda_runtime.h>
#include <cuda_fp16.h>
#include <cstdint>

#define B_ 2
#define T_ 2048
#define HID_ 2048
#define NH_ 16
#define KVH_ 4
#define HD_ 128
#define NQKV 3072
#define KDIM 2048

// fp32 QKV GEMM output
__device__ float g_qkv[(size_t)B_ * T_ * NQKV];
// fp16 GEMM operands
__device__ __half g_hid_h[(size_t)4096 * KDIM];
__device__ __half g_wqkv_h[(size_t)KDIM * NQKV];
__device__ __half g_wo_h[(size_t)KDIM * HID_];
__device__ __half g_ctx_h[(size_t)4096 * HID_];   // written by flash epilogue
// fp16 flash inputs
__device__ __half g_qf[(size_t)B_ * T_ * NH_ * HD_];
__device__ __half g_kf[(size_t)B_ * T_ * KVH_ * HD_];
__device__ __half g_vf[(size_t)B_ * T_ * KVH_ * HD_];

// ---------------------------------------------------------------------------
// helpers
// ---------------------------------------------------------------------------
__device__ __forceinline__ void cp16(uint32_t s, const void* g) {
    asm volatile("cp.async.cg.shared.global [%0], [%1], 16;\n" :: "r"(s), "l"(g));
}
__device__ __forceinline__ void cp_commit() {
    asm volatile("cp.async.commit_group;\n" ::);
}
__device__ __forceinline__ void mma_f16(float* c, const uint32_t* a, const uint32_t* b) {
    asm volatile(
        "mma.sync.aligned.m16n8k16.row.col.f32.f16.f16.f32 "
        "{%0,%1,%2,%3}, {%4,%5,%6,%7}, {%8,%9}, {%0,%1,%2,%3};\n"
        : "+f"(c[0]), "+f"(c[1]), "+f"(c[2]), "+f"(c[3])
        : "r"(a[0]), "r"(a[1]), "r"(a[2]), "r"(a[3]), "r"(b[0]), "r"(b[1]));
}
__device__ __forceinline__ void ldsm4(uint32_t* d, uint32_t addr) {
    asm volatile("ldmatrix.sync.aligned.m8n8.x4.shared.b16 {%0,%1,%2,%3}, [%4];\n"
                 : "=r"(d[0]), "=r"(d[1]), "=r"(d[2]), "=r"(d[3]) : "r"(addr));
}
__device__ __forceinline__ void ldsm4t(uint32_t* d, uint32_t addr) {
    asm volatile("ldmatrix.sync.aligned.m8n8.x4.trans.shared.b16 {%0,%1,%2,%3}, [%4];\n"
                 : "=r"(d[0]), "=r"(d[1]), "=r"(d[2]), "=r"(d[3]) : "r"(addr));
}
__device__ __forceinline__ float ex2(float x) {
    float r;
    asm("ex2.approx.f32 %0, %1;" : "=f"(r) : "f"(x));
    return r;
}
__device__ __forceinline__ uint32_t packh2(float a, float b) {
    __half2 t = __floats2half2_rn(a, b);
    return *(uint32_t*)&t;
}

// ---------------------------------------------------------------------------
// fp32 -> fp16 converts
// ---------------------------------------------------------------------------
__global__ void cvt_f16(const float* __restrict__ in, __half* __restrict__ out,
                        int total8) {
    int i = blockIdx.x * blockDim.x + threadIdx.x;
    if (i >= total8) return;
    float4 x0 = *(const float4*)(in + (size_t)i * 8);
    float4 x1 = *(const float4*)(in + (size_t)i * 8 + 4);
    __half2 h[4];
    h[0] = __floats2half2_rn(x0.x, x0.y);
    h[1] = __floats2half2_rn(x0.z, x0.w);
    h[2] = __floats2half2_rn(x1.x, x1.y);
    h[3] = __floats2half2_rn(x1.z, x1.w);
    *(uint4*)(out + (size_t)i * 8) = *(uint4*)h;
}
__global__ void cvt_f16_off(const float* __restrict__ W, __half* __restrict__ out,
                            int K, int N, int NO, int noff) {
    int i = blockIdx.x * blockDim.x + threadIdx.x;
    if (i >= K * N) return;
    int k = i / N, n = i - k * N;
    out[(size_t)k * NO + noff + n] = __float2half(W[i]);
}

// ---------------------------------------------------------------------------
// fp16 GEMM (proven config): C(M,N) fp32 = A(M,K) @ B(K,N).
// ---------------------------------------------------------------------------
#define GBM 128
#define GBN 128
#define GBK 64
#define GSTAGES 3
#define A_STAGE_BYTES (GBM * GBK * 2)
#define B_STAGE_BYTES (GBK * GBN * 2)

__global__ __launch_bounds__(256) void f16gemm(const __half* __restrict__ A,
                                               const __half* __restrict__ B,
                                               float* __restrict__ C,
                                               int M, int N, int K) {
    extern __shared__ char sm[];
    const uint32_t smBase = (uint32_t)__cvta_generic_to_shared(sm);
    const uint32_t aBase = smBase;
    const uint32_t bBase = smBase + GSTAGES * A_STAGE_BYTES;

    const int tid = threadIdx.x;
    const int bm = blockIdx.y, bn = blockIdx.x;
    const int warp = tid >> 5, lane = tid & 31;
    const int wm = warp >> 2;
    const int wn = warp & 3;

    float acc[4][4][4];
#pragma unroll
    for (int mi = 0; mi < 4; mi++)
#pragma unroll
        for (int ni = 0; ni < 4; ni++)
#pragma unroll
            for (int e = 0; e < 4; e++) acc[mi][ni][e] = 0.f;

    const int KT = K / GBK;

    auto load_stage = [&](int sidx, int kt) {
#pragma unroll
        for (int i = 0; i < 4; i++) {
            int q = tid + i * 256;
            int r = q >> 3, c = q & 7;
            const __half* g = A + (size_t)(bm * GBM + r) * K + kt * GBK + c * 8;
            uint32_t s = aBase + sidx * A_STAGE_BYTES + r * 128 + (((c ^ (r & 7)) & 7) << 4);
            cp16(s, g);
        }
#pragma unroll
        for (int i = 0; i < 4; i++) {
            int q = tid + i * 256;
            int r = q >> 4, c = q & 15;
            const __half* g = B + (size_t)(kt * GBK + r) * N + bn * GBN + c * 8;
            int ch = (c & 8) | ((c ^ (r & 7)) & 7);
            uint32_t s = bBase + sidx * B_STAGE_BYTES + r * 256 + (ch << 4);
            cp16(s, g);
        }
    };

#pragma unroll
    for (int s = 0; s < GSTAGES - 1; s++) {
        load_stage(s, s);
        cp_commit();
    }
    asm volatile("cp.async.wait_group %0;\n" :: "n"(GSTAGES - 2));
    __syncthreads();

    const int a_row = wm * 64 + (lane & 15);
    const int a_col8 = (lane >> 4) * 8;
    const int b_row = (lane & 15);
    const int b_colb = wn * 32 + (lane >> 4) * 8;

    for (int kt = 0; kt < KT; kt++) {
        const int cur = kt % GSTAGES;
        if (kt + GSTAGES - 1 < KT) load_stage((kt + GSTAGES - 1) % GSTAGES, kt + GSTAGES - 1);
        cp_commit();

        const uint32_t aS = aBase + cur * A_STAGE_BYTES;
        const uint32_t bS = bBase + cur * B_STAGE_BYTES;

#pragma unroll
        for (int ks = 0; ks < GBK / 16; ks++) {
            uint32_t af[4][4];
#pragma unroll
            for (int mi = 0; mi < 4; mi++) {
                int row = a_row + mi * 16;
                int col = ks * 16 + a_col8;
                uint32_t addr = aS + row * 128 + ((((col >> 3) ^ (row & 7)) & 7) << 4);
                ldsm4(af[mi], addr);
            }
            uint32_t bfr[4][2];
#pragma unroll
            for (int np = 0; np < 2; np++) {
                int row = ks * 16 + b_row;
                int col = b_colb + np * 16;
                int ch = (col >> 3);
                ch = (ch & 8) | ((ch ^ (row & 7)) & 7);
                uint32_t addr = bS + row * 256 + (ch << 4);
                uint32_t tmp[4];
                ldsm4t(tmp, addr);
                bfr[np * 2][0] = tmp[0]; bfr[np * 2][1] = tmp[1];
                bfr[np * 2 + 1][0] = tmp[2]; bfr[np * 2 + 1][1] = tmp[3];
            }
#pragma unroll
            for (int mi = 0; mi < 4; mi++)
#pragma unroll
                for (int ni = 0; ni < 4; ni++)
                    mma_f16(acc[mi][ni], af[mi], bfr[ni]);
        }

        asm volatile("cp.async.wait_group %0;\n" :: "n"(GSTAGES - 2));
        __syncthreads();
    }

#pragma unroll
    for (int mi = 0; mi < 4; mi++) {
#pragma unroll
        for (int ni = 0; ni < 4; ni++) {
            int row = bm * GBM + wm * 64 + mi * 16 + (lane >> 2);
            int col = bn * GBN + wn * 32 + ni * 8 + (lane & 3) * 2;
            *(float2*)&C[(size_t)row * N + col] = make_float2(acc[mi][ni][0], acc[mi][ni][1]);
            *(float2*)&C[(size_t)(row + 8) * N + col] = make_float2(acc[mi][ni][2], acc[mi][ni][3]);
        }
    }
}

// ---------------------------------------------------------------------------
// RoPE -> fp16 (reads fused fp32 qkv at head offset hoff; scale folded)
// ---------------------------------------------------------------------------
__global__ void rope_f16(const float* __restrict__ x, int xstride, int hoff,
                         const float* __restrict__ cosp, const float* __restrict__ sinp,
                         __half* __restrict__ o, int nheads, float scale) {
    int idx = blockIdx.x * blockDim.x + threadIdx.x;
    int total = B_ * T_ * nheads * 64;
    if (idx >= total) return;
    int d = idx & 63;
    int h = (idx >> 6) % nheads;
    int tok = idx / (64 * nheads);
    int t = tok & (T_ - 1);
    size_t ib = (size_t)tok * xstride + hoff + h * HD_;
    size_t ob = ((size_t)tok * nheads + h) * HD_;
    float c1 = cosp[t * HD_ + d], s1 = sinp[t * HD_ + d];
    float c2 = cosp[t * HD_ + d + 64], s2 = sinp[t * HD_ + d + 64];
    float x1 = x[ib + d], x2 = x[ib + d + 64];
    o[ob + d] = __float2half((x1 * c1 - x2 * s1) * scale);
    o[ob + d + 64] = __float2half((x2 * c2 + x1 * s2) * scale);
}

// V slice of fused qkv (cols 2560..3071) -> dense fp16
__global__ void cvt_v_f16(const float* __restrict__ in, __half* __restrict__ o, int total) {
    int i = blockIdx.x * blockDim.x + threadIdx.x;
    if (i >= total) return;
    int tok = i >> 9, r = i & 511;
    o[i] = __float2half(in[(size_t)tok * NQKV + 2560 + r]);
}

// ---------------------------------------------------------------------------
// fp16 tensor-core flash attention. BM=BN=64, 128 threads, 48 KB smem
// (Q,K,V single tiles -> 4 CTAs/SM). Warp owns 16 rows; softmax warp-local.
// ---------------------------------------------------------------------------
#define FTILE (64 * 128 * 2)

__global__ __launch_bounds__(128) void flash_f16(const __half* __restrict__ Qf,
                                                 const __half* __restrict__ Kf,
                                                 const __half* __restrict__ Vf,
                                                 __half* __restrict__ ctxH) {
    extern __shared__ char sm[];
    const uint32_t smBase = (uint32_t)__cvta_generic_to_shared(sm);
    const uint32_t sQ = smBase;
    const uint32_t sK = smBase + FTILE;
    const uint32_t sV = smBase + 2 * FTILE;

    const int tid = threadIdx.x;
    const int warp = tid >> 5, lane = tid & 31;
    const int qtile = blockIdx.x;
    const int h = blockIdx.y;
    const int b = blockIdx.z;
    const int kvh = h / (NH_ / KVH_);
    const int q0 = qtile * 64;

    auto loadTile = [&](uint32_t sbase, const __half* g, size_t gbase, int gstride) {
#pragma unroll
        for (int i = 0; i < 8; i++) {
            int q = tid + i * 128;
            int r = q >> 4, c = q & 15;
            int ch = (c & 8) | ((c ^ (r & 7)) & 7);
            cp16(sbase + r * 256 + (ch << 4), g + gbase + (size_t)r * gstride + c * 8);
        }
    };

    const size_t qgb = ((size_t)(b * T_ + q0) * NH_ + h) * HD_;
    loadTile(sQ, Qf, qgb, NH_ * HD_);
    cp_commit();

    float oAcc[16][4];
#pragma unroll
    for (int j = 0; j < 16; j++)
#pragma unroll
        for (int e = 0; e < 4; e++) oAcc[j][e] = 0.f;
    float mrow[2] = {-1e30f, -1e30f};
    float lrow[2] = {0.f, 0.f};

    for (int t0 = 0; t0 <= qtile; t0++) {
        const int s0 = t0 * 64;
        __syncthreads();
        const size_t kgb = ((size_t)(b * T_ + s0) * KVH_ + kvh) * HD_;
        loadTile(sK, Kf, kgb, KVH_ * HD_);
        loadTile(sV, Vf, kgb, KVH_ * HD_);
        cp_commit();
        asm volatile("cp.async.wait_group 0;\n" ::);
        __syncthreads();

        // ---- S = Q K^T ----
        float sAcc[8][4];
#pragma unroll
        for (int j = 0; j < 8; j++)
#pragma unroll
            for (int e = 0; e < 4; e++) sAcc[j][e] = 0.f;

#pragma unroll
        for (int ks = 0; ks < 8; ks++) {
            int arow = warp * 16 + (lane & 15);
            int ac = ks * 2 + (lane >> 4);
            int ach = (ac & 8) | ((ac ^ (arow & 7)) & 7);
            uint32_t a4[4];
            ldsm4(a4, sQ + arow * 256 + (ach << 4));
            int krow_base = (lane & 7) + ((lane >> 4) & 1) * 8;
            int kc = ks * 2 + ((lane >> 3) & 1);
#pragma unroll
            for (int jp = 0; jp < 4; jp++) {
                int krow = jp * 16 + krow_base;
                int kch = (kc & 8) | ((kc ^ (krow & 7)) & 7);
                uint32_t b4[4];
                ldsm4(b4, sK + krow * 256 + (kch << 4));
                mma_f16(sAcc[jp * 2], a4, b4);
                mma_f16(sAcc[jp * 2 + 1], a4, &b4[2]);
            }
        }

        if (t0 == qtile) {
            int r0 = warp * 16 + (lane >> 2);
#pragma unroll
            for (int j = 0; j < 8; j++) {
                int cb = j * 8 + (lane & 3) * 2;
                if (cb > r0) sAcc[j][0] = -1e30f;
                if (cb + 1 > r0) sAcc[j][1] = -1e30f;
                if (cb > r0 + 8) sAcc[j][2] = -1e30f;
                if (cb + 1 > r0 + 8) sAcc[j][3] = -1e30f;
            }
        }

        // ---- online softmax ----
        float mx0 = -1e30f, mx1 = -1e30f;
#pragma unroll
        for (int j = 0; j < 8; j++) {
            mx0 = fmaxf(mx0, fmaxf(sAcc[j][0], sAcc[j][1]));
            mx1 = fmaxf(mx1, fmaxf(sAcc[j][2], sAcc[j][3]));
        }
        mx0 = fmaxf(mx0, __shfl_xor_sync(0xffffffffu, mx0, 1));
        mx0 = fmaxf(mx0, __shfl_xor_sync(0xffffffffu, mx0, 2));
        mx1 = fmaxf(mx1, __shfl_xor_sync(0xffffffffu, mx1, 1));
        mx1 = fmaxf(mx1, __shfl_xor_sync(0xffffffffu, mx1, 2));
        float mn0 = fmaxf(mrow[0], mx0);
        float mn1 = fmaxf(mrow[1], mx1);
        float al0 = ex2(mrow[0] - mn0);
        float al1 = ex2(mrow[1] - mn1);
        mrow[0] = mn0;
        mrow[1] = mn1;
        float sum0 = 0.f, sum1 = 0.f;
#pragma unroll
        for (int j = 0; j < 8; j++) {
            sAcc[j][0] = ex2(sAcc[j][0] - mn0);
            sAcc[j][1] = ex2(sAcc[j][1] - mn0);
            sAcc[j][2] = ex2(sAcc[j][2] - mn1);
            sAcc[j][3] = ex2(sAcc[j][3] - mn1);
            sum0 += sAcc[j][0] + sAcc[j][1];
            sum1 += sAcc[j][2] + sAcc[j][3];
        }
        sum0 += __shfl_xor_sync(0xffffffffu, sum0, 1);
        sum0 += __shfl_xor_sync(0xffffffffu, sum0, 2);
        sum1 += __shfl_xor_sync(0xffffffffu, sum1, 1);
        sum1 += __shfl_xor_sync(0xffffffffu, sum1, 2);
        lrow[0] = lrow[0] * al0 + sum0;
        lrow[1] = lrow[1] * al1 + sum1;
#pragma unroll
        for (int j = 0; j < 16; j++) {
            oAcc[j][0] *= al0;
            oAcc[j][1] *= al0;
            oAcc[j][2] *= al1;
            oAcc[j][3] *= al1;
        }

        // ---- O += P V ----
        int vrow_b = (lane & 15);
        int vcb = (lane >> 4);
#pragma unroll
        for (int kt = 0; kt < 4; kt++) {
            uint32_t pf[4];
            pf[0] = packh2(sAcc[2 * kt][0], sAcc[2 * kt][1]);
            pf[1] = packh2(sAcc[2 * kt][2], sAcc[2 * kt][3]);
            pf[2] = packh2(sAcc[2 * kt + 1][0], sAcc[2 * kt + 1][1]);
            pf[3] = packh2(sAcc[2 * kt + 1][2], sAcc[2 * kt + 1][3]);
            int vrow = kt * 16 + vrow_b;
#pragma unroll
            for (int jp2 = 0; jp2 < 8; jp2++) {
                int vc = jp2 * 2 + vcb;
                int vch = (vc & 8) | ((vc ^ (vrow & 7)) & 7);
                uint32_t v4[4];
                ldsm4t(v4, sV + vrow * 256 + (vch << 4));
                mma_f16(oAcc[jp2 * 2], pf, v4);
                mma_f16(oAcc[jp2 * 2 + 1], pf, &v4[2]);
            }
        }
    }

    // epilogue: normalize, write fp16 ctx (b,t,h,d)
    float inv0 = 1.f / lrow[0];
    float inv1 = 1.f / lrow[1];
    int r0 = q0 + warp * 16 + (lane >> 2);
    size_t row0 = (size_t)(b * T_ + r0) * HID_;
    size_t row1 = row0 + (size_t)8 * HID_;
#pragma unroll
    for (int j = 0; j < 16; j++) {
        int col = h * HD_ + j * 8 + (lane & 3) * 2;
        uint32_t v01 = packh2(oAcc[j][0] * inv0, oAcc[j][1] * inv0);
        uint32_t v23 = packh2(oAcc[j][2] * inv1, oAcc[j][3] * inv1);
        *(uint32_t*)(ctxH + row0 + col) = v01;
        *(uint32_t*)(ctxH + row1 + col) = v23;
    }
}

// ---------------------------------------------------------------------------
// Launch
// ---------------------------------------------------------------------------
extern "C" void kernel_launch(void* const* d_in, const int* in_sizes, int n_in,
                              void* d_out, int out_size) {
    const float* hidden = (const float*)d_in[0];
    const float* cosp = (const float*)d_in[2];
    const float* sinp = (const float*)d_in[3];
    const float* Wq = (const float*)d_in[4];
    const float* Wk = (const float*)d_in[5];
    const float* Wv = (const float*)d_in[6];
    const float* Wo = (const float*)d_in[7];
    float* out = (float*)d_out;

    float* qkv;
    __half *hid_h, *wqkv_h, *wo_h, *ctx_h, *qf, *kf, *vf;
    cudaGetSymbolAddress((void**)&qkv, g_qkv);
    cudaGetSymbolAddress((void**)&hid_h, g_hid_h);
    cudaGetSymbolAddress((void**)&wqkv_h, g_wqkv_h);
    cudaGetSymbolAddress((void**)&wo_h, g_wo_h);
    cudaGetSymbolAddress((void**)&ctx_h, g_ctx_h);
    cudaGetSymbolAddress((void**)&qf, g_qf);
    cudaGetSymbolAddress((void**)&kf, g_kf);
    cudaGetSymbolAddress((void**)&vf, g_vf);

    const int M = B_ * T_;  // 4096

    constexpr int GEMM_SMEM = GSTAGES * (A_STAGE_BYTES + B_STAGE_BYTES);  // 96 KB
    cudaFuncSetAttribute(f16gemm, cudaFuncAttributeMaxDynamicSharedMemorySize, GEMM_SMEM);
    cudaFuncSetAttribute(flash_f16, cudaFuncAttributeMaxDynamicSharedMemorySize, 3 * FTILE);

    // fp32 -> fp16 converts
    cvt_f16<<<(M * KDIM / 8 + 255) / 256, 256>>>(hidden, hid_h, M * KDIM / 8);
    cvt_f16_off<<<(KDIM * 2048 + 255) / 256, 256>>>(Wq, wqkv_h, KDIM, 2048, NQKV, 0);
    cvt_f16_off<<<(KDIM * 512 + 255) / 256, 256>>>(Wk, wqkv_h, KDIM, 512, NQKV, 2048);
    cvt_f16_off<<<(KDIM * 512 + 255) / 256, 256>>>(Wv, wqkv_h, KDIM, 512, NQKV, 2560);
    cvt_f16_off<<<(KDIM * 2048 + 255) / 256, 256>>>(Wo, wo_h, KDIM, 2048, 2048, 0);

    // fused QKV projection
    f16gemm<<<dim3(NQKV / GBN, M / GBM), 256, GEMM_SMEM>>>(hid_h, wqkv_h, qkv, M, NQKV, KDIM);

    // RoPE -> fp16 flash inputs (q carries log2e/sqrt(HD))
    const float qscale = 1.4426950408889634f * 0.08838834764831845f;
    rope_f16<<<(B_ * T_ * NH_ * 64 + 255) / 256, 256>>>(qkv, NQKV, 0, cosp, sinp, qf, NH_, qscale);
    rope_f16<<<(B_ * T_ * KVH_ * 64 + 255) / 256, 256>>>(qkv, NQKV, 2048, cosp, sinp, kf, KVH_, 1.0f);
    cvt_v_f16<<<(M * 512 + 255) / 256, 256>>>(qkv, vf, M * 512);

    // fp16 flash attention -> fp16 ctx
    flash_f16<<<dim3(T_ / 64, NH_, B_), 128, 3 * FTILE>>>(qf, kf, vf, ctx_h);

    // output projection
    f16gemm<<<dim3(2048 / GBN, M / GBM), 256, GEMM_SMEM>>>(ctx_h, wo_h, out, M, 2048, KDIM);
}